// round 15
// baseline (speedup 1.0000x reference)
#include <cuda_runtime.h>
#include <cuda_fp16.h>
#include <cstdint>

#define NN 2048
#define KA 64
#define ELLW 64
#define NITER 10
#define RPB 4   // rows per block in iter kernel

#define MSCALE 4194304.0f            // 2^22: lifts s~1e-7 into fp16 range
#define INV_MSCALE (1.0f / 4194304.0f)

// ---------------- static device scratch (allocation-free contract) ----------
// Sentinel index NN points at zero pad rows/slots (device globals zero-init;
// pad rows never written, so they stay zero across graph replays).
__device__ unsigned short g_ell[2][NN * ELLW];
__device__ unsigned short g_ellT[ELLW / 4][NN][4];  // permuted+swizzled+sorted adj2
__device__ int    g_degr[2][NN];                     // raw degrees
__device__ int    g_deg1p[NN];                       // padded graph-1 degrees
__device__ int    g_deg2p[NN];                       // permuted padded graph-2 degrees
__device__ int    g_sorted[NN];                      // jp -> original column j
__device__ int    g_pos[NN];                         // original j -> jp
__device__ float  g_Nn[2][(NN + 1) * KA];            // +1 zero pad row
__device__ float  g_P[2][NN * KA];
__device__ float  g_q[(size_t)NN * NN];              // q, permuted cols
__device__ __half g_hts[(size_t)NN * NN];            // 0.18*Ht*MSCALE, permuted cols
__device__ __half g_Mh[2][(size_t)(NN + 1) * NN];    // scaled fp16 M, permuted cols

// bank-group swizzle for 16B granules: involution, keeps sentinel 2048 fixed
__device__ __forceinline__ unsigned phi(unsigned k) { return k ^ ((k >> 3) & 7u); }

// ---------------- packed f32x2 helpers --------------------------------------
__device__ __forceinline__ unsigned long long pk2(float lo, float hi) {
    unsigned long long r;
    asm("mov.b64 %0, {%1, %2};" : "=l"(r) : "f"(lo), "f"(hi));
    return r;
}
__device__ __forceinline__ void fma2(unsigned long long& d, unsigned long long a,
                                     unsigned long long b) {
    asm("fma.rn.f32x2 %0, %1, %2, %0;" : "+l"(d) : "l"(a), "l"(b));
}
__device__ __forceinline__ unsigned long long add2(unsigned long long a,
                                                   unsigned long long b) {
    unsigned long long r;
    asm("add.rn.f32x2 %0, %1, %2;" : "=l"(r) : "l"(a), "l"(b));
    return r;
}
__device__ __forceinline__ void upk2(unsigned long long v, float& lo, float& hi) {
    asm("mov.b64 {%0, %1}, %2;" : "=f"(lo), "=f"(hi) : "l"(v));
}

// ---------------- setup: ELL adjacency build + attr normalize ---------------
__global__ void setup_kernel(const float* __restrict__ A1,
                             const float* __restrict__ A2,
                             const float* __restrict__ N1,
                             const float* __restrict__ N2) {
    int b = blockIdx.x;
    int warp = threadIdx.x >> 5;
    int lane = threadIdx.x & 31;
    if (b < 512) {
        int sel = b >> 8;
        int row = ((b & 255) << 3) + warp;
        const float* A = sel ? A2 : A1;
        const float* r = A + (size_t)row * NN;
        unsigned short* lst = &g_ell[sel][row * ELLW];
        lst[lane] = (unsigned short)NN;
        lst[lane + 32] = (unsigned short)NN;
        __syncwarp();
        int base = 0;
        for (int c0 = 0; c0 < NN; c0 += 32) {
            bool p = (r[c0 + lane] != 0.0f);
            unsigned m = __ballot_sync(0xffffffffu, p);
            if (p) {
                int pos = base + __popc(m & ((1u << lane) - 1u));
                if (pos < ELLW) lst[pos] = (unsigned short)(c0 + lane);
            }
            base += __popc(m);
        }
        if (lane == 0) {
            int d = (base < ELLW) ? base : ELLW;
            g_degr[sel][row] = d;
            if (sel == 0) g_deg1p[row] = (d + 3) & ~3;
        }
    } else {
        int idx = ((b - 512) << 3) + warp;  // 0..4095
        int sel = idx >> 11;
        int row = idx & 2047;
        const float* Nin = sel ? N2 : N1;
        size_t base = (size_t)row * KA;
        float a = Nin[base + lane];
        float c2 = Nin[base + 32 + lane];
        float ss = a * a + c2 * c2;
#pragma unroll
        for (int o = 16; o; o >>= 1) ss += __shfl_xor_sync(0xffffffffu, ss, o);
        float nrm = sqrtf(ss);
        float inv = (nrm > 0.0f) ? (1.0f / nrm) : 0.0f;
        g_Nn[sel][base + lane] = a * inv;
        g_Nn[sel][base + 32 + lane] = c2 * inv;
    }
}

// ---------------- stable degree-rank of graph-2 columns ---------------------
__global__ void sort_kernel() {
    __shared__ int red[256];
    int j = blockIdx.x;
    int tid = threadIdx.x;
    int dj = g_degr[1][j];
    int cnt = 0;
    for (int k = tid; k < NN; k += 256) {
        int dk = g_degr[1][k];
        cnt += (dk < dj) || (dk == dj && k < j);
    }
    red[tid] = cnt;
    __syncthreads();
    for (int off = 128; off; off >>= 1) {
        if (tid < off) red[tid] += red[tid + off];
        __syncthreads();
    }
    if (tid == 0) {
        int rank = red[0];
        g_pos[j] = rank;
        g_sorted[rank] = j;
        g_deg2p[rank] = (dj + 3) & ~3;
    }
}

// ---------------- build permuted/swizzled/conflict-sorted adj2 lists --------
__global__ void ellT_kernel() {
    int jp = blockIdx.x * 8 + (threadIdx.x >> 5);
    if ((threadIdx.x & 31) != 0) return;
    int j = g_sorted[jp];
    int d = g_degr[1][j];
    const unsigned short* lst = &g_ell[1][j * ELLW];
    unsigned short bkt[8][ELLW];
    int cnt[8] = {0, 0, 0, 0, 0, 0, 0, 0};
    for (int p = 0; p < d; p++) {
        unsigned pp = phi((unsigned)g_pos[lst[p]]);
        int g = (int)((pp - (unsigned)jp) & 7u);
        bkt[g][cnt[g]++] = (unsigned short)pp;
    }
    unsigned short tmp[ELLW];
    int n = 0;
    int ptr[8] = {0, 0, 0, 0, 0, 0, 0, 0};
    while (n < d) {
        for (int g = 0; g < 8; g++)
            if (ptr[g] < cnt[g]) tmp[n++] = bkt[g][ptr[g]++];
    }
    for (int p = d; p < ELLW; p++) tmp[p] = (unsigned short)NN;
    for (int p = 0; p < ELLW; p++)
        g_ellT[p >> 2][jp][p & 3] = tmp[p];
}

// ---------------- P = A @ Nn (add-only SpMM over attrs) ---------------------
__global__ void spmm_attr_both() {
    int sel = blockIdx.x >> 11;
    int row = blockIdx.x & 2047;
    int lane = threadIdx.x;  // 64 threads = KA
    const unsigned short* lst = &g_ell[sel][row * ELLW];
    int deg = g_degr[sel][row];
    float acc = 0.0f;
    for (int p = 0; p < deg; p++)
        acc += g_Nn[sel][(size_t)lst[p] * KA + lane];
    g_P[sel][(size_t)row * KA + lane] = acc;
}

// ---------------- q = rsqrt(Nm*dm)*Nm; write q + hts + fp16 M0 --------------
// Column side (graph-2) runs in PERMUTED space via g_sorted.
__global__ void __launch_bounds__(256) q_m0_kernel(const float* __restrict__ H) {
    __shared__ float sXT[64][68];  // [k][row]
    __shared__ float sYT[64][68];  // [k][col-row]
    int tx = threadIdx.x, ty = threadIdx.y;
    int t = ty * 16 + tx;
    int gi = blockIdx.y * 64, gj = blockIdx.x * 64;

    unsigned long long nm2[4][2], dm2[4][2];

    // ---- phase 1: Nm += N1n N2n^T (cols permuted) ----
#pragma unroll
    for (int pass = 0; pass < 4; pass++) {
        int idx = pass * 256 + t;
        int row = idx >> 4;
        int k4 = (idx & 15) * 4;
        int oj = g_sorted[gj + row];
        float4 a = *(const float4*)&g_Nn[0][(size_t)(gi + row) * KA + k4];
        float4 bvec = *(const float4*)&g_Nn[1][(size_t)oj * KA + k4];
        sXT[k4 + 0][row] = a.x; sXT[k4 + 1][row] = a.y;
        sXT[k4 + 2][row] = a.z; sXT[k4 + 3][row] = a.w;
        sYT[k4 + 0][row] = bvec.x; sYT[k4 + 1][row] = bvec.y;
        sYT[k4 + 2][row] = bvec.z; sYT[k4 + 3][row] = bvec.w;
    }
    __syncthreads();
#pragma unroll
    for (int r = 0; r < 4; r++) { nm2[r][0] = 0ull; nm2[r][1] = 0ull; }
#pragma unroll 4
    for (int k = 0; k < KA; k++) {
        float4 a = *(const float4*)&sXT[k][ty * 4];
        float4 bb = *(const float4*)&sYT[k][tx * 4];
        unsigned long long b01 = pk2(bb.x, bb.y), b23 = pk2(bb.z, bb.w);
        float av[4] = {a.x, a.y, a.z, a.w};
#pragma unroll
        for (int r = 0; r < 4; r++) {
            unsigned long long ad = pk2(av[r], av[r]);
            fma2(nm2[r][0], ad, b01);
            fma2(nm2[r][1], ad, b23);
        }
    }
    __syncthreads();

    // ---- phase 2: dm += P1 P2^T (cols permuted) ----
#pragma unroll
    for (int pass = 0; pass < 4; pass++) {
        int idx = pass * 256 + t;
        int row = idx >> 4;
        int k4 = (idx & 15) * 4;
        int oj = g_sorted[gj + row];
        float4 a = *(const float4*)&g_P[0][(size_t)(gi + row) * KA + k4];
        float4 bvec = *(const float4*)&g_P[1][(size_t)oj * KA + k4];
        sXT[k4 + 0][row] = a.x; sXT[k4 + 1][row] = a.y;
        sXT[k4 + 2][row] = a.z; sXT[k4 + 3][row] = a.w;
        sYT[k4 + 0][row] = bvec.x; sYT[k4 + 1][row] = bvec.y;
        sYT[k4 + 2][row] = bvec.z; sYT[k4 + 3][row] = bvec.w;
    }
    __syncthreads();
#pragma unroll
    for (int r = 0; r < 4; r++) { dm2[r][0] = 0ull; dm2[r][1] = 0ull; }
#pragma unroll 4
    for (int k = 0; k < KA; k++) {
        float4 a = *(const float4*)&sXT[k][ty * 4];
        float4 bb = *(const float4*)&sYT[k][tx * 4];
        unsigned long long b01 = pk2(bb.x, bb.y), b23 = pk2(bb.z, bb.w);
        float av[4] = {a.x, a.y, a.z, a.w};
#pragma unroll
        for (int r = 0; r < 4; r++) {
            unsigned long long ad = pk2(av[r], av[r]);
            fma2(dm2[r][0], ad, b01);
            fma2(dm2[r][1], ad, b23);
        }
    }
    __syncthreads();

    // ---- phase 3: H tile (transposed, permuted rows of H) ----
#pragma unroll
    for (int pass = 0; pass < 4; pass++) {
        int idx = pass * 256 + t;
        int jl = idx >> 4;
        int i4 = (idx & 15) * 4;
        float4 h = *(const float4*)&H[(size_t)g_sorted[gj + jl] * NN + gi + i4];
        *(float4*)&sXT[jl][i4] = h;
    }
    __syncthreads();

#pragma unroll
    for (int r = 0; r < 4; r++) {
        int i = gi + ty * 4 + r;
        size_t base = (size_t)i * NN + gj + tx * 4;
        float nm[4], dm[4];
        upk2(nm2[r][0], nm[0], nm[1]); upk2(nm2[r][1], nm[2], nm[3]);
        upk2(dm2[r][0], dm[0], dm[1]); upk2(dm2[r][1], dm[2], dm[3]);
        float4 qv;
        float m[4], hs[4];
#pragma unroll
        for (int c = 0; c < 4; c++) {
            float D = nm[c] * dm[c];
            float dd = (D > 0.0f) ? (1.0f / sqrtf(D)) : 0.0f;
            float q = dd * nm[c];
            ((float*)&qv)[c] = q;
            float ht = sXT[tx * 4 + c][ty * 4 + r];
            m[c] = q * ht * MSCALE;            // M0 = q .* h, scaled
            hs[c] = 0.18f * ht * MSCALE;       // hts ~ 0.18, fp16-safe
        }
        *(float4*)&g_q[base] = qv;
        __half2 hs01 = __floats2half2_rn(hs[0], hs[1]);
        __half2 hs23 = __floats2half2_rn(hs[2], hs[3]);
        uint2 hsp;
        hsp.x = *(unsigned*)&hs01;
        hsp.y = *(unsigned*)&hs23;
        *(uint2*)&g_hts[base] = hsp;
        __half2 h01 = __floats2half2_rn(m[0], m[1]);
        __half2 h23 = __floats2half2_rn(m[2], m[3]);
        uint2 pk;
        pk.x = *(unsigned*)&h01;
        pk.y = *(unsigned*)&h23;
        *(uint2*)&g_Mh[0][base] = pk;
    }
}

// ---------------- fused iteration: S = A1 (q.*s) A2 ; s' ; M' ---------------
// (512,4): single wave at grid=512. M fp16; acc fp32; stage-2 ADD2 packed;
// epilogue in scaled domain: s_sc = hts + 0.82*q*S_sc, M' = q*s_sc.
__global__ void __launch_bounds__(512, 4) iter_kernel(int par,
                                                      float* __restrict__ sOut,
                                                      int writeS, int writeM) {
    __shared__ float acc_s[(NN + 1) * RPB];  // granule phi(k) holds [k][r0..3]
    const __half* __restrict__ Min = g_Mh[par];
    __half* __restrict__ Mout = g_Mh[par ^ 1];
    int i0 = blockIdx.x * RPB;
    int tid = threadIdx.x;

    // stage 1: acc[k][r] = sum_{p in adj1(i0+r)} M[p][k]; 4-wide fp16 gathers
    const uint2* __restrict__ Min2 = (const uint2*)Min;
#pragma unroll
    for (int r = 0; r < RPB; r++) {
        float4 acc = make_float4(0.f, 0.f, 0.f, 0.f);
        const unsigned short* lst = &g_ell[0][(i0 + r) * ELLW];
        int pd = g_deg1p[i0 + r];  // pre-padded to multiple of 4
        for (int p = 0; p < pd; p += 4) {
            ushort4 rr = *(const ushort4*)(lst + p);  // uniform -> broadcast
            uint2 u0 = Min2[(size_t)rr.x * (NN / 4) + tid];
            uint2 u1 = Min2[(size_t)rr.y * (NN / 4) + tid];
            uint2 u2 = Min2[(size_t)rr.z * (NN / 4) + tid];
            uint2 u3 = Min2[(size_t)rr.w * (NN / 4) + tid];
#pragma unroll
            for (int s = 0; s < 4; s++) {
                uint2 u = (s == 0) ? u0 : (s == 1) ? u1 : (s == 2) ? u2 : u3;
                float2 f0 = __half22float2(*(__half2*)&u.x);
                float2 f1 = __half22float2(*(__half2*)&u.y);
                acc.x += f0.x; acc.y += f0.y; acc.z += f1.x; acc.w += f1.y;
            }
        }
        float vv[4] = {acc.x, acc.y, acc.z, acc.w};
#pragma unroll
        for (int c = 0; c < 4; c++)
            acc_s[phi(tid * 4 + c) * RPB + r] = vv[c];
    }
    if (tid == 0) {  // sentinel granule
        acc_s[NN * RPB + 0] = 0.f; acc_s[NN * RPB + 1] = 0.f;
        acc_s[NN * RPB + 2] = 0.f; acc_s[NN * RPB + 3] = 0.f;
    }
    __syncthreads();

    // stage 2: per permuted column jp, gather adj2; ulonglong2 LDS.128 +
    // packed f32x2 adds (8 ADD2 per 4-gather group instead of 12 FADD).
    const ulonglong2* __restrict__ acc8 = (const ulonglong2*)acc_s;
#pragma unroll
    for (int m = 0; m < NN / 512; m++) {
        int j = tid + m * 512;
        int pd = g_deg2p[j];  // pre-padded to multiple of 4
        int pgmax = __reduce_max_sync(0xffffffffu, pd) >> 2;
        unsigned long long sAlo = 0ull, sAhi = 0ull, sBlo = 0ull, sBhi = 0ull;
        for (int pg = 0; pg < pgmax; pg++) {
            ushort4 ii = *(const ushort4*)g_ellT[pg][j];  // coalesced
            ulonglong2 v0 = acc8[ii.x], v1 = acc8[ii.y];
            ulonglong2 v2 = acc8[ii.z], v3 = acc8[ii.w];
            sAlo = add2(sAlo, add2(v0.x, v1.x));
            sAhi = add2(sAhi, add2(v0.y, v1.y));
            sBlo = add2(sBlo, add2(v2.x, v3.x));
            sBhi = add2(sBhi, add2(v2.y, v3.y));
        }
        unsigned long long slo = add2(sAlo, sBlo);
        unsigned long long shi = add2(sAhi, sBhi);
        float S[RPB];
        upk2(slo, S[0], S[1]);
        upk2(shi, S[2], S[3]);
        int jorig = writeS ? g_sorted[j] : 0;
#pragma unroll
        for (int r = 0; r < RPB; r++) {
            size_t idx = (size_t)(i0 + r) * NN + j;
            float q = g_q[idx];
            float hts = __half2float(g_hts[idx]);
            float ssc = fmaf(0.82f * q, S[r], hts);   // scaled-domain s
            if (writeM) Mout[idx] = __float2half_rn(q * ssc);
            if (writeS) sOut[(size_t)(i0 + r) * NN + jorig] = ssc * INV_MSCALE;
        }
    }
}

// ---------------- launch ----------------------------------------------------
extern "C" void kernel_launch(void* const* d_in, const int* in_sizes, int n_in,
                              void* d_out, int out_size) {
    const float* A1 = (const float*)d_in[0];
    const float* A2 = (const float*)d_in[1];
    const float* N1 = (const float*)d_in[2];
    const float* N2 = (const float*)d_in[3];
    const float* H  = (const float*)d_in[4];
    float* out = (float*)d_out;

    setup_kernel<<<1024, 256>>>(A1, A2, N1, N2);       // 1
    sort_kernel<<<NN, 256>>>();                        // 2
    ellT_kernel<<<NN / 8, 256>>>();                    // 3
    spmm_attr_both<<<4096, 64>>>();                    // 4
    q_m0_kernel<<<dim3(32, 32), dim3(16, 16)>>>(H);    // 5

    for (int it = 0; it < NITER; it++) {               // 6..15
        int last = (it == NITER - 1);
        iter_kernel<<<NN / RPB, 512>>>(it & 1, out, last, !last);
    }
}

// round 16
// speedup vs baseline: 1.0609x; 1.0609x over previous
#include <cuda_runtime.h>
#include <cuda_fp16.h>
#include <cstdint>

#define NN 2048
#define KA 64
#define ELLW 64
#define NITER 10
#define RPB 4   // rows per block in iter kernel

#define MSCALE 4194304.0f            // 2^22: lifts s~1e-7 into fp16 range
#define DESCALE (0.82f / 4194304.0f) // folded 0.82/MSCALE for epilogue

// ---------------- static device scratch (allocation-free contract) ----------
// Sentinel index NN points at zero pad rows/slots (device globals zero-init;
// pad rows never written, so they stay zero across graph replays).
__device__ unsigned short g_ell[2][NN * ELLW];
__device__ unsigned short g_ellT[ELLW / 4][NN][4];  // permuted+swizzled+sorted adj2
__device__ int    g_degr[2][NN];                     // raw degrees
__device__ int    g_deg1p[NN];                       // padded graph-1 degrees
__device__ int    g_deg2p[NN];                       // permuted padded graph-2 degrees
__device__ int    g_sorted[NN];                      // jp -> original column j
__device__ int    g_pos[NN];                         // original j -> jp
__device__ float  g_Nn[2][(NN + 1) * KA];            // +1 zero pad row
__device__ float  g_P[2][NN * KA];
__device__ float2 g_qh[(size_t)NN * NN];             // {q, 0.18*Ht}, permuted cols
__device__ __half g_Mh[2][(size_t)(NN + 1) * NN];    // scaled fp16 M, permuted cols

// bank-group swizzle for 16B granules: involution, keeps sentinel 2048 fixed
__device__ __forceinline__ unsigned phi(unsigned k) { return k ^ ((k >> 3) & 7u); }

// ---------------- packed f32x2 helpers --------------------------------------
__device__ __forceinline__ unsigned long long pk2(float lo, float hi) {
    unsigned long long r;
    asm("mov.b64 %0, {%1, %2};" : "=l"(r) : "f"(lo), "f"(hi));
    return r;
}
__device__ __forceinline__ void fma2(unsigned long long& d, unsigned long long a,
                                     unsigned long long b) {
    asm("fma.rn.f32x2 %0, %1, %2, %0;" : "+l"(d) : "l"(a), "l"(b));
}
__device__ __forceinline__ void upk2(unsigned long long v, float& lo, float& hi) {
    asm("mov.b64 {%0, %1}, %2;" : "=f"(lo), "=f"(hi) : "l"(v));
}

// ---------------- setup: ELL adjacency build + attr normalize ---------------
__global__ void setup_kernel(const float* __restrict__ A1,
                             const float* __restrict__ A2,
                             const float* __restrict__ N1,
                             const float* __restrict__ N2) {
    int b = blockIdx.x;
    int warp = threadIdx.x >> 5;
    int lane = threadIdx.x & 31;
    if (b < 512) {
        int sel = b >> 8;
        int row = ((b & 255) << 3) + warp;
        const float* A = sel ? A2 : A1;
        const float* r = A + (size_t)row * NN;
        unsigned short* lst = &g_ell[sel][row * ELLW];
        lst[lane] = (unsigned short)NN;
        lst[lane + 32] = (unsigned short)NN;
        __syncwarp();
        int base = 0;
        for (int c0 = 0; c0 < NN; c0 += 32) {
            bool p = (r[c0 + lane] != 0.0f);
            unsigned m = __ballot_sync(0xffffffffu, p);
            if (p) {
                int pos = base + __popc(m & ((1u << lane) - 1u));
                if (pos < ELLW) lst[pos] = (unsigned short)(c0 + lane);
            }
            base += __popc(m);
        }
        if (lane == 0) {
            int d = (base < ELLW) ? base : ELLW;
            g_degr[sel][row] = d;
            if (sel == 0) g_deg1p[row] = (d + 3) & ~3;
        }
    } else {
        int idx = ((b - 512) << 3) + warp;  // 0..4095
        int sel = idx >> 11;
        int row = idx & 2047;
        const float* Nin = sel ? N2 : N1;
        size_t base = (size_t)row * KA;
        float a = Nin[base + lane];
        float c2 = Nin[base + 32 + lane];
        float ss = a * a + c2 * c2;
#pragma unroll
        for (int o = 16; o; o >>= 1) ss += __shfl_xor_sync(0xffffffffu, ss, o);
        float nrm = sqrtf(ss);
        float inv = (nrm > 0.0f) ? (1.0f / nrm) : 0.0f;
        g_Nn[sel][base + lane] = a * inv;
        g_Nn[sel][base + 32 + lane] = c2 * inv;
    }
}

// ---------------- stable degree-rank of graph-2 columns ---------------------
__global__ void sort_kernel() {
    __shared__ int red[256];
    int j = blockIdx.x;
    int tid = threadIdx.x;
    int dj = g_degr[1][j];
    int cnt = 0;
    for (int k = tid; k < NN; k += 256) {
        int dk = g_degr[1][k];
        cnt += (dk < dj) || (dk == dj && k < j);
    }
    red[tid] = cnt;
    __syncthreads();
    for (int off = 128; off; off >>= 1) {
        if (tid < off) red[tid] += red[tid + off];
        __syncthreads();
    }
    if (tid == 0) {
        int rank = red[0];
        g_pos[j] = rank;
        g_sorted[rank] = j;
        g_deg2p[rank] = (dj + 3) & ~3;
    }
}

// ---------------- build permuted/swizzled/conflict-sorted adj2 lists --------
__global__ void ellT_kernel() {
    int jp = blockIdx.x * 8 + (threadIdx.x >> 5);
    if ((threadIdx.x & 31) != 0) return;
    int j = g_sorted[jp];
    int d = g_degr[1][j];
    const unsigned short* lst = &g_ell[1][j * ELLW];
    unsigned short bkt[8][ELLW];
    int cnt[8] = {0, 0, 0, 0, 0, 0, 0, 0};
    for (int p = 0; p < d; p++) {
        unsigned pp = phi((unsigned)g_pos[lst[p]]);
        int g = (int)((pp - (unsigned)jp) & 7u);
        bkt[g][cnt[g]++] = (unsigned short)pp;
    }
    unsigned short tmp[ELLW];
    int n = 0;
    int ptr[8] = {0, 0, 0, 0, 0, 0, 0, 0};
    while (n < d) {
        for (int g = 0; g < 8; g++)
            if (ptr[g] < cnt[g]) tmp[n++] = bkt[g][ptr[g]++];
    }
    for (int p = d; p < ELLW; p++) tmp[p] = (unsigned short)NN;
    for (int p = 0; p < ELLW; p++)
        g_ellT[p >> 2][jp][p & 3] = tmp[p];
}

// ---------------- P = A @ Nn (add-only SpMM over attrs) ---------------------
// Unrolled x4 over sentinel-padded lists: 4 independent gathers in flight.
__global__ void spmm_attr_both() {
    int sel = blockIdx.x >> 11;
    int row = blockIdx.x & 2047;
    int lane = threadIdx.x;  // 64 threads = KA
    const unsigned short* lst = &g_ell[sel][row * ELLW];
    int pd = (g_degr[sel][row] + 3) & ~3;  // sentinel rows are zero
    float a0 = 0.f, a1 = 0.f, a2 = 0.f, a3 = 0.f;
    for (int p = 0; p < pd; p += 4) {
        ushort4 rr = *(const ushort4*)(lst + p);
        a0 += g_Nn[sel][(size_t)rr.x * KA + lane];
        a1 += g_Nn[sel][(size_t)rr.y * KA + lane];
        a2 += g_Nn[sel][(size_t)rr.z * KA + lane];
        a3 += g_Nn[sel][(size_t)rr.w * KA + lane];
    }
    g_P[sel][(size_t)row * KA + lane] = (a0 + a1) + (a2 + a3);
}

// ---------------- q = rsqrt(Nm*dm)*Nm; {q, 0.18Ht} + fp16 M0 ----------------
// Column side (graph-2) runs in PERMUTED space via g_sorted.
__global__ void __launch_bounds__(256) q_m0_kernel(const float* __restrict__ H) {
    __shared__ float sXT[64][68];  // [k][row]
    __shared__ float sYT[64][68];  // [k][col-row]
    int tx = threadIdx.x, ty = threadIdx.y;
    int t = ty * 16 + tx;
    int gi = blockIdx.y * 64, gj = blockIdx.x * 64;

    unsigned long long nm2[4][2], dm2[4][2];

    // ---- phase 1: Nm += N1n N2n^T (cols permuted) ----
#pragma unroll
    for (int pass = 0; pass < 4; pass++) {
        int idx = pass * 256 + t;
        int row = idx >> 4;
        int k4 = (idx & 15) * 4;
        int oj = g_sorted[gj + row];
        float4 a = *(const float4*)&g_Nn[0][(size_t)(gi + row) * KA + k4];
        float4 bvec = *(const float4*)&g_Nn[1][(size_t)oj * KA + k4];
        sXT[k4 + 0][row] = a.x; sXT[k4 + 1][row] = a.y;
        sXT[k4 + 2][row] = a.z; sXT[k4 + 3][row] = a.w;
        sYT[k4 + 0][row] = bvec.x; sYT[k4 + 1][row] = bvec.y;
        sYT[k4 + 2][row] = bvec.z; sYT[k4 + 3][row] = bvec.w;
    }
    __syncthreads();
#pragma unroll
    for (int r = 0; r < 4; r++) { nm2[r][0] = 0ull; nm2[r][1] = 0ull; }
#pragma unroll 4
    for (int k = 0; k < KA; k++) {
        float4 a = *(const float4*)&sXT[k][ty * 4];
        float4 bb = *(const float4*)&sYT[k][tx * 4];
        unsigned long long b01 = pk2(bb.x, bb.y), b23 = pk2(bb.z, bb.w);
        float av[4] = {a.x, a.y, a.z, a.w};
#pragma unroll
        for (int r = 0; r < 4; r++) {
            unsigned long long ad = pk2(av[r], av[r]);
            fma2(nm2[r][0], ad, b01);
            fma2(nm2[r][1], ad, b23);
        }
    }
    __syncthreads();

    // ---- phase 2: dm += P1 P2^T (cols permuted) ----
#pragma unroll
    for (int pass = 0; pass < 4; pass++) {
        int idx = pass * 256 + t;
        int row = idx >> 4;
        int k4 = (idx & 15) * 4;
        int oj = g_sorted[gj + row];
        float4 a = *(const float4*)&g_P[0][(size_t)(gi + row) * KA + k4];
        float4 bvec = *(const float4*)&g_P[1][(size_t)oj * KA + k4];
        sXT[k4 + 0][row] = a.x; sXT[k4 + 1][row] = a.y;
        sXT[k4 + 2][row] = a.z; sXT[k4 + 3][row] = a.w;
        sYT[k4 + 0][row] = bvec.x; sYT[k4 + 1][row] = bvec.y;
        sYT[k4 + 2][row] = bvec.z; sYT[k4 + 3][row] = bvec.w;
    }
    __syncthreads();
#pragma unroll
    for (int r = 0; r < 4; r++) { dm2[r][0] = 0ull; dm2[r][1] = 0ull; }
#pragma unroll 4
    for (int k = 0; k < KA; k++) {
        float4 a = *(const float4*)&sXT[k][ty * 4];
        float4 bb = *(const float4*)&sYT[k][tx * 4];
        unsigned long long b01 = pk2(bb.x, bb.y), b23 = pk2(bb.z, bb.w);
        float av[4] = {a.x, a.y, a.z, a.w};
#pragma unroll
        for (int r = 0; r < 4; r++) {
            unsigned long long ad = pk2(av[r], av[r]);
            fma2(dm2[r][0], ad, b01);
            fma2(dm2[r][1], ad, b23);
        }
    }
    __syncthreads();

    // ---- phase 3: H tile (transposed, permuted rows of H) ----
#pragma unroll
    for (int pass = 0; pass < 4; pass++) {
        int idx = pass * 256 + t;
        int jl = idx >> 4;
        int i4 = (idx & 15) * 4;
        float4 h = *(const float4*)&H[(size_t)g_sorted[gj + jl] * NN + gi + i4];
        *(float4*)&sXT[jl][i4] = h;
    }
    __syncthreads();

#pragma unroll
    for (int r = 0; r < 4; r++) {
        int i = gi + ty * 4 + r;
        size_t base = (size_t)i * NN + gj + tx * 4;
        float nm[4], dm[4];
        upk2(nm2[r][0], nm[0], nm[1]); upk2(nm2[r][1], nm[2], nm[3]);
        upk2(dm2[r][0], dm[0], dm[1]); upk2(dm2[r][1], dm[2], dm[3]);
        float q[4], m[4];
        float4 qh0, qh1;
#pragma unroll
        for (int c = 0; c < 4; c++) {
            float D = nm[c] * dm[c];
            float dd = (D > 0.0f) ? (1.0f / sqrtf(D)) : 0.0f;
            q[c] = dd * nm[c];
            float ht = sXT[tx * 4 + c][ty * 4 + r];
            m[c] = q[c] * ht * MSCALE;  // M0 = q .* h, scaled
            if (c < 2) { ((float*)&qh0)[c * 2] = q[c]; ((float*)&qh0)[c * 2 + 1] = 0.18f * ht; }
            else       { ((float*)&qh1)[(c - 2) * 2] = q[c]; ((float*)&qh1)[(c - 2) * 2 + 1] = 0.18f * ht; }
        }
        *(float4*)&g_qh[base] = qh0;
        *(float4*)&g_qh[base + 2] = qh1;
        __half2 h01 = __floats2half2_rn(m[0], m[1]);
        __half2 h23 = __floats2half2_rn(m[2], m[3]);
        uint2 pk;
        pk.x = *(unsigned*)&h01;
        pk.y = *(unsigned*)&h23;
        *(uint2*)&g_Mh[0][base] = pk;
    }
}

// ---------------- fused iteration: S = A1 (q.*s) A2 ; s' ; M' ---------------
// (512,4): single wave at grid=512. M fp16 (halved gather traffic), acc fp32.
// Columns degree-sorted => warp-uniform stage-2 trip counts. (Proven 497us
// form; the packed-f32x2 variant regressed via register pairing at 32 regs.)
__global__ void __launch_bounds__(512, 4) iter_kernel(int par,
                                                      float* __restrict__ sOut,
                                                      int writeS, int writeM) {
    __shared__ float acc_s[(NN + 1) * RPB];  // granule phi(k) holds [k][r0..3]
    const __half* __restrict__ Min = g_Mh[par];
    __half* __restrict__ Mout = g_Mh[par ^ 1];
    int i0 = blockIdx.x * RPB;
    int tid = threadIdx.x;

    // stage 1: acc[k][r] = sum_{p in adj1(i0+r)} M[p][k]; 4-wide fp16 gathers
    // (uint2 = 4 halves), fp32 accumulate, swizzled scalar STS.
    const uint2* __restrict__ Min2 = (const uint2*)Min;
#pragma unroll
    for (int r = 0; r < RPB; r++) {
        float4 acc = make_float4(0.f, 0.f, 0.f, 0.f);
        const unsigned short* lst = &g_ell[0][(i0 + r) * ELLW];
        int pd = g_deg1p[i0 + r];  // pre-padded to multiple of 4
        for (int p = 0; p < pd; p += 4) {
            ushort4 rr = *(const ushort4*)(lst + p);  // uniform -> broadcast
            uint2 u0 = Min2[(size_t)rr.x * (NN / 4) + tid];
            uint2 u1 = Min2[(size_t)rr.y * (NN / 4) + tid];
            uint2 u2 = Min2[(size_t)rr.z * (NN / 4) + tid];
            uint2 u3 = Min2[(size_t)rr.w * (NN / 4) + tid];
#pragma unroll
            for (int s = 0; s < 4; s++) {
                uint2 u = (s == 0) ? u0 : (s == 1) ? u1 : (s == 2) ? u2 : u3;
                float2 f0 = __half22float2(*(__half2*)&u.x);
                float2 f1 = __half22float2(*(__half2*)&u.y);
                acc.x += f0.x; acc.y += f0.y; acc.z += f1.x; acc.w += f1.y;
            }
        }
        float vv[4] = {acc.x, acc.y, acc.z, acc.w};
#pragma unroll
        for (int c = 0; c < 4; c++)
            acc_s[phi(tid * 4 + c) * RPB + r] = vv[c];
    }
    if (tid == 0) {  // sentinel granule
        acc_s[NN * RPB + 0] = 0.f; acc_s[NN * RPB + 1] = 0.f;
        acc_s[NN * RPB + 2] = 0.f; acc_s[NN * RPB + 3] = 0.f;
    }
    __syncthreads();

    // stage 2: per permuted column jp, gather adj2 (pre-swizzled,
    // conflict-sorted, degree-uniform per warp); 4 indices / ushort4 load.
    const float4* __restrict__ acc4 = (const float4*)acc_s;
#pragma unroll
    for (int m = 0; m < NN / 512; m++) {
        int j = tid + m * 512;
        int pd = g_deg2p[j];  // pre-padded to multiple of 4
        int pgmax = __reduce_max_sync(0xffffffffu, pd) >> 2;
        float4 s0 = make_float4(0.f, 0.f, 0.f, 0.f);
        float4 s1 = make_float4(0.f, 0.f, 0.f, 0.f);
#pragma unroll 2
        for (int pg = 0; pg < pgmax; pg++) {
            ushort4 ii = *(const ushort4*)g_ellT[pg][j];  // coalesced
            float4 v0 = acc4[ii.x], v1 = acc4[ii.y];
            float4 v2 = acc4[ii.z], v3 = acc4[ii.w];
            s0.x += v0.x + v1.x; s0.y += v0.y + v1.y;
            s0.z += v0.z + v1.z; s0.w += v0.w + v1.w;
            s1.x += v2.x + v3.x; s1.y += v2.y + v3.y;
            s1.z += v2.z + v3.z; s1.w += v2.w + v3.w;
        }
        float S[RPB] = {s0.x + s1.x, s0.y + s1.y, s0.z + s1.z, s0.w + s1.w};
        int jorig = writeS ? g_sorted[j] : 0;
#pragma unroll
        for (int r = 0; r < RPB; r++) {
            size_t idx = (size_t)(i0 + r) * NN + j;
            float2 qh = g_qh[idx];  // {q, 0.18*Ht}
            float sv = qh.y + DESCALE * (qh.x * S[r]);
            if (writeM) Mout[idx] = __float2half_rn(qh.x * sv * MSCALE);
            if (writeS) sOut[(size_t)(i0 + r) * NN + jorig] = sv;
        }
    }
}

// ---------------- launch ----------------------------------------------------
extern "C" void kernel_launch(void* const* d_in, const int* in_sizes, int n_in,
                              void* d_out, int out_size) {
    const float* A1 = (const float*)d_in[0];
    const float* A2 = (const float*)d_in[1];
    const float* N1 = (const float*)d_in[2];
    const float* N2 = (const float*)d_in[3];
    const float* H  = (const float*)d_in[4];
    float* out = (float*)d_out;

    setup_kernel<<<1024, 256>>>(A1, A2, N1, N2);       // 1
    sort_kernel<<<NN, 256>>>();                        // 2
    ellT_kernel<<<NN / 8, 256>>>();                    // 3
    spmm_attr_both<<<4096, 64>>>();                    // 4
    q_m0_kernel<<<dim3(32, 32), dim3(16, 16)>>>(H);    // 5

    for (int it = 0; it < NITER; it++) {               // 6..15
        int last = (it == NITER - 1);
        iter_kernel<<<NN / RPB, 512>>>(it & 1, out, last, !last);
    }
}

// round 17
// speedup vs baseline: 1.0662x; 1.0049x over previous
#include <cuda_runtime.h>
#include <cuda_fp16.h>
#include <cstdint>

#define NN 2048
#define KA 64
#define ELLW 64
#define NITER 10
#define RPB 4   // rows per block in iter kernel

#define MSCALE 4194304.0f            // 2^22: lifts s~1e-7 into fp16 range
#define DESCALE (0.82f / 4194304.0f) // folded 0.82/MSCALE for epilogue

// ---------------- static device scratch (allocation-free contract) ----------
// Sentinel index NN points at zero pad rows/slots (device globals zero-init;
// pad rows never written, so they stay zero across graph replays).
__device__ unsigned short g_ell[2][NN * ELLW];
__device__ unsigned short g_ellT[ELLW / 4][NN][4];  // permuted+swizzled+sorted adj2
__device__ int    g_degr[2][NN];                     // raw degrees
__device__ int    g_deg1p[NN];                       // padded graph-1 degrees
__device__ int    g_deg2p[NN];                       // permuted padded graph-2 degrees
__device__ int    g_sorted[NN];                      // jp -> original column j
__device__ int    g_pos[NN];                         // original j -> jp
__device__ float  g_Nn[2][(NN + 1) * KA];            // +1 zero pad row
__device__ float  g_P[2][NN * KA];
__device__ float2 g_qh[(size_t)NN * NN];             // {q, 0.18*Ht}, permuted cols
__device__ __half g_Mh[2][(size_t)(NN + 1) * NN];    // scaled fp16 M, permuted cols

// bank-group swizzle for 16B granules: involution, keeps sentinel 2048 fixed
__device__ __forceinline__ unsigned phi(unsigned k) { return k ^ ((k >> 3) & 7u); }

// ---------------- packed f32x2 helpers --------------------------------------
__device__ __forceinline__ unsigned long long pk2(float lo, float hi) {
    unsigned long long r;
    asm("mov.b64 %0, {%1, %2};" : "=l"(r) : "f"(lo), "f"(hi));
    return r;
}
__device__ __forceinline__ void fma2(unsigned long long& d, unsigned long long a,
                                     unsigned long long b) {
    asm("fma.rn.f32x2 %0, %1, %2, %0;" : "+l"(d) : "l"(a), "l"(b));
}
__device__ __forceinline__ void upk2(unsigned long long v, float& lo, float& hi) {
    asm("mov.b64 {%0, %1}, %2;" : "=f"(lo), "=f"(hi) : "l"(v));
}

// ---------------- setup: ELL adjacency build + attr normalize ---------------
__global__ void setup_kernel(const float* __restrict__ A1,
                             const float* __restrict__ A2,
                             const float* __restrict__ N1,
                             const float* __restrict__ N2) {
    int b = blockIdx.x;
    int warp = threadIdx.x >> 5;
    int lane = threadIdx.x & 31;
    if (b < 512) {
        int sel = b >> 8;
        int row = ((b & 255) << 3) + warp;
        const float* A = sel ? A2 : A1;
        const float* r = A + (size_t)row * NN;
        unsigned short* lst = &g_ell[sel][row * ELLW];
        lst[lane] = (unsigned short)NN;
        lst[lane + 32] = (unsigned short)NN;
        __syncwarp();
        int base = 0;
        for (int c0 = 0; c0 < NN; c0 += 32) {
            bool p = (r[c0 + lane] != 0.0f);
            unsigned m = __ballot_sync(0xffffffffu, p);
            if (p) {
                int pos = base + __popc(m & ((1u << lane) - 1u));
                if (pos < ELLW) lst[pos] = (unsigned short)(c0 + lane);
            }
            base += __popc(m);
        }
        if (lane == 0) {
            int d = (base < ELLW) ? base : ELLW;
            g_degr[sel][row] = d;
            if (sel == 0) g_deg1p[row] = (d + 3) & ~3;
        }
    } else {
        int idx = ((b - 512) << 3) + warp;  // 0..4095
        int sel = idx >> 11;
        int row = idx & 2047;
        const float* Nin = sel ? N2 : N1;
        size_t base = (size_t)row * KA;
        float a = Nin[base + lane];
        float c2 = Nin[base + 32 + lane];
        float ss = a * a + c2 * c2;
#pragma unroll
        for (int o = 16; o; o >>= 1) ss += __shfl_xor_sync(0xffffffffu, ss, o);
        float nrm = sqrtf(ss);
        float inv = (nrm > 0.0f) ? (1.0f / nrm) : 0.0f;
        g_Nn[sel][base + lane] = a * inv;
        g_Nn[sel][base + 32 + lane] = c2 * inv;
    }
}

// ---------------- stable degree-rank of graph-2 columns ---------------------
__global__ void sort_kernel() {
    __shared__ int red[256];
    int j = blockIdx.x;
    int tid = threadIdx.x;
    int dj = g_degr[1][j];
    int cnt = 0;
    for (int k = tid; k < NN; k += 256) {
        int dk = g_degr[1][k];
        cnt += (dk < dj) || (dk == dj && k < j);
    }
    red[tid] = cnt;
    __syncthreads();
    for (int off = 128; off; off >>= 1) {
        if (tid < off) red[tid] += red[tid + off];
        __syncthreads();
    }
    if (tid == 0) {
        int rank = red[0];
        g_pos[j] = rank;
        g_sorted[rank] = j;
        g_deg2p[rank] = (dj + 3) & ~3;
    }
}

// ---------------- build permuted/swizzled/conflict-sorted adj2 lists --------
__global__ void ellT_kernel() {
    int jp = blockIdx.x * 8 + (threadIdx.x >> 5);
    if ((threadIdx.x & 31) != 0) return;
    int j = g_sorted[jp];
    int d = g_degr[1][j];
    const unsigned short* lst = &g_ell[1][j * ELLW];
    unsigned short bkt[8][ELLW];
    int cnt[8] = {0, 0, 0, 0, 0, 0, 0, 0};
    for (int p = 0; p < d; p++) {
        unsigned pp = phi((unsigned)g_pos[lst[p]]);
        int g = (int)((pp - (unsigned)jp) & 7u);
        bkt[g][cnt[g]++] = (unsigned short)pp;
    }
    unsigned short tmp[ELLW];
    int n = 0;
    int ptr[8] = {0, 0, 0, 0, 0, 0, 0, 0};
    while (n < d) {
        for (int g = 0; g < 8; g++)
            if (ptr[g] < cnt[g]) tmp[n++] = bkt[g][ptr[g]++];
    }
    for (int p = d; p < ELLW; p++) tmp[p] = (unsigned short)NN;
    for (int p = 0; p < ELLW; p++)
        g_ellT[p >> 2][jp][p & 3] = tmp[p];
}

// ---------------- P = A @ Nn (add-only SpMM over attrs) ---------------------
__global__ void spmm_attr_both() {
    int sel = blockIdx.x >> 11;
    int row = blockIdx.x & 2047;
    int lane = threadIdx.x;  // 64 threads = KA
    const ushort4* lst = (const ushort4*)&g_ell[sel][row * ELLW];
    int pg = ((g_degr[sel][row] + 3) & ~3) >> 2;  // sentinel rows are zero
    float a0 = 0.f, a1 = 0.f, a2 = 0.f, a3 = 0.f;
    for (int p = 0; p < pg; p++) {
        ushort4 rr = lst[p];
        a0 += g_Nn[sel][(size_t)rr.x * KA + lane];
        a1 += g_Nn[sel][(size_t)rr.y * KA + lane];
        a2 += g_Nn[sel][(size_t)rr.z * KA + lane];
        a3 += g_Nn[sel][(size_t)rr.w * KA + lane];
    }
    g_P[sel][(size_t)row * KA + lane] = (a0 + a1) + (a2 + a3);
}

// ---------------- q = rsqrt(Nm*dm)*Nm; {q, 0.18Ht} + fp16 M0 ----------------
// Column side (graph-2) runs in PERMUTED space via g_sorted.
__global__ void __launch_bounds__(256) q_m0_kernel(const float* __restrict__ H) {
    __shared__ float sXT[64][68];  // [k][row]
    __shared__ float sYT[64][68];  // [k][col-row]
    int tx = threadIdx.x, ty = threadIdx.y;
    int t = ty * 16 + tx;
    int gi = blockIdx.y * 64, gj = blockIdx.x * 64;

    unsigned long long nm2[4][2], dm2[4][2];

    // ---- phase 1: Nm += N1n N2n^T (cols permuted) ----
#pragma unroll
    for (int pass = 0; pass < 4; pass++) {
        int idx = pass * 256 + t;
        int row = idx >> 4;
        int k4 = (idx & 15) * 4;
        int oj = g_sorted[gj + row];
        float4 a = *(const float4*)&g_Nn[0][(size_t)(gi + row) * KA + k4];
        float4 bvec = *(const float4*)&g_Nn[1][(size_t)oj * KA + k4];
        sXT[k4 + 0][row] = a.x; sXT[k4 + 1][row] = a.y;
        sXT[k4 + 2][row] = a.z; sXT[k4 + 3][row] = a.w;
        sYT[k4 + 0][row] = bvec.x; sYT[k4 + 1][row] = bvec.y;
        sYT[k4 + 2][row] = bvec.z; sYT[k4 + 3][row] = bvec.w;
    }
    __syncthreads();
#pragma unroll
    for (int r = 0; r < 4; r++) { nm2[r][0] = 0ull; nm2[r][1] = 0ull; }
#pragma unroll 4
    for (int k = 0; k < KA; k++) {
        float4 a = *(const float4*)&sXT[k][ty * 4];
        float4 bb = *(const float4*)&sYT[k][tx * 4];
        unsigned long long b01 = pk2(bb.x, bb.y), b23 = pk2(bb.z, bb.w);
        float av[4] = {a.x, a.y, a.z, a.w};
#pragma unroll
        for (int r = 0; r < 4; r++) {
            unsigned long long ad = pk2(av[r], av[r]);
            fma2(nm2[r][0], ad, b01);
            fma2(nm2[r][1], ad, b23);
        }
    }
    __syncthreads();

    // ---- phase 2: dm += P1 P2^T (cols permuted) ----
#pragma unroll
    for (int pass = 0; pass < 4; pass++) {
        int idx = pass * 256 + t;
        int row = idx >> 4;
        int k4 = (idx & 15) * 4;
        int oj = g_sorted[gj + row];
        float4 a = *(const float4*)&g_P[0][(size_t)(gi + row) * KA + k4];
        float4 bvec = *(const float4*)&g_P[1][(size_t)oj * KA + k4];
        sXT[k4 + 0][row] = a.x; sXT[k4 + 1][row] = a.y;
        sXT[k4 + 2][row] = a.z; sXT[k4 + 3][row] = a.w;
        sYT[k4 + 0][row] = bvec.x; sYT[k4 + 1][row] = bvec.y;
        sYT[k4 + 2][row] = bvec.z; sYT[k4 + 3][row] = bvec.w;
    }
    __syncthreads();
#pragma unroll
    for (int r = 0; r < 4; r++) { dm2[r][0] = 0ull; dm2[r][1] = 0ull; }
#pragma unroll 4
    for (int k = 0; k < KA; k++) {
        float4 a = *(const float4*)&sXT[k][ty * 4];
        float4 bb = *(const float4*)&sYT[k][tx * 4];
        unsigned long long b01 = pk2(bb.x, bb.y), b23 = pk2(bb.z, bb.w);
        float av[4] = {a.x, a.y, a.z, a.w};
#pragma unroll
        for (int r = 0; r < 4; r++) {
            unsigned long long ad = pk2(av[r], av[r]);
            fma2(dm2[r][0], ad, b01);
            fma2(dm2[r][1], ad, b23);
        }
    }
    __syncthreads();

    // ---- phase 3: H tile (transposed, permuted rows of H) ----
#pragma unroll
    for (int pass = 0; pass < 4; pass++) {
        int idx = pass * 256 + t;
        int jl = idx >> 4;
        int i4 = (idx & 15) * 4;
        float4 h = *(const float4*)&H[(size_t)g_sorted[gj + jl] * NN + gi + i4];
        *(float4*)&sXT[jl][i4] = h;
    }
    __syncthreads();

#pragma unroll
    for (int r = 0; r < 4; r++) {
        int i = gi + ty * 4 + r;
        size_t base = (size_t)i * NN + gj + tx * 4;
        float nm[4], dm[4];
        upk2(nm2[r][0], nm[0], nm[1]); upk2(nm2[r][1], nm[2], nm[3]);
        upk2(dm2[r][0], dm[0], dm[1]); upk2(dm2[r][1], dm[2], dm[3]);
        float q[4], m[4];
        float4 qh0, qh1;
#pragma unroll
        for (int c = 0; c < 4; c++) {
            float D = nm[c] * dm[c];
            float dd = (D > 0.0f) ? (1.0f / sqrtf(D)) : 0.0f;
            q[c] = dd * nm[c];
            float ht = sXT[tx * 4 + c][ty * 4 + r];
            m[c] = q[c] * ht * MSCALE;  // M0 = q .* h, scaled
            if (c < 2) { ((float*)&qh0)[c * 2] = q[c]; ((float*)&qh0)[c * 2 + 1] = 0.18f * ht; }
            else       { ((float*)&qh1)[(c - 2) * 2] = q[c]; ((float*)&qh1)[(c - 2) * 2 + 1] = 0.18f * ht; }
        }
        *(float4*)&g_qh[base] = qh0;
        *(float4*)&g_qh[base + 2] = qh1;
        __half2 h01 = __floats2half2_rn(m[0], m[1]);
        __half2 h23 = __floats2half2_rn(m[2], m[3]);
        uint2 pk;
        pk.x = *(unsigned*)&h01;
        pk.y = *(unsigned*)&h23;
        *(uint2*)&g_Mh[0][base] = pk;
    }
}

// ---------------- fused iteration: S = A1 (q.*s) A2 ; s' ; M' ---------------
// (512,4): single wave at grid=512. M fp16 (halved gather traffic), acc fp32.
// Columns degree-sorted => warp-uniform stage-2 trip counts.
__global__ void __launch_bounds__(512, 4) iter_kernel(int par,
                                                      float* __restrict__ sOut,
                                                      int writeS, int writeM) {
    __shared__ float acc_s[(NN + 1) * RPB];  // granule phi(k) holds [k][r0..3]
    const __half* __restrict__ Min = g_Mh[par];
    __half* __restrict__ Mout = g_Mh[par ^ 1];
    int i0 = blockIdx.x * RPB;
    int tid = threadIdx.x;

    // stage 1: acc[k][r] = sum_{p in adj1(i0+r)} M[p][k]; 4-wide fp16 gathers
    // (uint2 = 4 halves), fp32 accumulate, swizzled scalar STS.
    const uint2* __restrict__ Min2 = (const uint2*)Min;
#pragma unroll
    for (int r = 0; r < RPB; r++) {
        float4 acc = make_float4(0.f, 0.f, 0.f, 0.f);
        const ushort4* lst = (const ushort4*)&g_ell[0][(i0 + r) * ELLW];
        int pg1 = g_deg1p[i0 + r] >> 2;  // pre-padded to multiple of 4
        for (int p = 0; p < pg1; p++) {
            ushort4 rr = lst[p];  // uniform -> broadcast
            uint2 u0 = Min2[(size_t)rr.x * (NN / 4) + tid];
            uint2 u1 = Min2[(size_t)rr.y * (NN / 4) + tid];
            uint2 u2 = Min2[(size_t)rr.z * (NN / 4) + tid];
            uint2 u3 = Min2[(size_t)rr.w * (NN / 4) + tid];
#pragma unroll
            for (int s = 0; s < 4; s++) {
                uint2 u = (s == 0) ? u0 : (s == 1) ? u1 : (s == 2) ? u2 : u3;
                float2 f0 = __half22float2(*(__half2*)&u.x);
                float2 f1 = __half22float2(*(__half2*)&u.y);
                acc.x += f0.x; acc.y += f0.y; acc.z += f1.x; acc.w += f1.y;
            }
        }
        float vv[4] = {acc.x, acc.y, acc.z, acc.w};
#pragma unroll
        for (int c = 0; c < 4; c++)
            acc_s[phi(tid * 4 + c) * RPB + r] = vv[c];
    }
    if (tid == 0) {  // sentinel granule
        acc_s[NN * RPB + 0] = 0.f; acc_s[NN * RPB + 1] = 0.f;
        acc_s[NN * RPB + 2] = 0.f; acc_s[NN * RPB + 3] = 0.f;
    }
    __syncthreads();

    // stage 2: per permuted column jp, gather adj2 (pre-swizzled,
    // conflict-sorted, degree-uniform per warp); 4 indices / ushort4 load.
    const float4* __restrict__ acc4 = (const float4*)acc_s;
#pragma unroll
    for (int m = 0; m < NN / 512; m++) {
        int j = tid + m * 512;
        int pd = g_deg2p[j];  // pre-padded to multiple of 4
        int pgmax = __reduce_max_sync(0xffffffffu, pd) >> 2;
        float4 s0 = make_float4(0.f, 0.f, 0.f, 0.f);
        float4 s1 = make_float4(0.f, 0.f, 0.f, 0.f);
#pragma unroll 4
        for (int pg = 0; pg < pgmax; pg++) {
            ushort4 ii = *(const ushort4*)g_ellT[pg][j];  // coalesced
            float4 v0 = acc4[ii.x], v1 = acc4[ii.y];
            float4 v2 = acc4[ii.z], v3 = acc4[ii.w];
            s0.x += v0.x + v1.x; s0.y += v0.y + v1.y;
            s0.z += v0.z + v1.z; s0.w += v0.w + v1.w;
            s1.x += v2.x + v3.x; s1.y += v2.y + v3.y;
            s1.z += v2.z + v3.z; s1.w += v2.w + v3.w;
        }
        float S[RPB] = {s0.x + s1.x, s0.y + s1.y, s0.z + s1.z, s0.w + s1.w};
        int jorig = writeS ? g_sorted[j] : 0;
        // batched epilogue: 4 independent qh loads in flight (s0/s1 now dead)
        size_t idx0 = (size_t)i0 * NN + j;
        float2 qha = g_qh[idx0];
        float2 qhb = g_qh[idx0 + NN];
        float2 qhc = g_qh[idx0 + 2 * NN];
        float2 qhd = g_qh[idx0 + 3 * NN];
        float sva = qha.y + DESCALE * (qha.x * S[0]);
        float svb = qhb.y + DESCALE * (qhb.x * S[1]);
        float svc = qhc.y + DESCALE * (qhc.x * S[2]);
        float svd = qhd.y + DESCALE * (qhd.x * S[3]);
        if (writeM) {
            Mout[idx0]          = __float2half_rn(qha.x * sva * MSCALE);
            Mout[idx0 + NN]     = __float2half_rn(qhb.x * svb * MSCALE);
            Mout[idx0 + 2 * NN] = __float2half_rn(qhc.x * svc * MSCALE);
            Mout[idx0 + 3 * NN] = __float2half_rn(qhd.x * svd * MSCALE);
        }
        if (writeS) {
            size_t o0 = (size_t)i0 * NN + jorig;
            sOut[o0]          = sva;
            sOut[o0 + NN]     = svb;
            sOut[o0 + 2 * NN] = svc;
            sOut[o0 + 3 * NN] = svd;
        }
    }
}

// ---------------- launch ----------------------------------------------------
extern "C" void kernel_launch(void* const* d_in, const int* in_sizes, int n_in,
                              void* d_out, int out_size) {
    const float* A1 = (const float*)d_in[0];
    const float* A2 = (const float*)d_in[1];
    const float* N1 = (const float*)d_in[2];
    const float* N2 = (const float*)d_in[3];
    const float* H  = (const float*)d_in[4];
    float* out = (float*)d_out;

    setup_kernel<<<1024, 256>>>(A1, A2, N1, N2);       // 1
    sort_kernel<<<NN, 256>>>();                        // 2
    ellT_kernel<<<NN / 8, 256>>>();                    // 3
    spmm_attr_both<<<4096, 64>>>();                    // 4
    q_m0_kernel<<<dim3(32, 32), dim3(16, 16)>>>(H);    // 5

    for (int it = 0; it < NITER; it++) {               // 6..15
        int last = (it == NITER - 1);
        iter_kernel<<<NN / RPB, 512>>>(it & 1, out, last, !last);
    }
}